// round 13
// baseline (speedup 1.0000x reference)
#include <cuda_runtime.h>
#include <cuda_bf16.h>

// LSTMForecastModel: B=4096, T=128, OUT=64, H=200.
// R12 = R11 (mma.sync m16n8k16, bf16x3 split, fp32 accum) +
//  (a) double-buffered h smem -> 2 syncthreads per step instead of 4
//  (b) layer-1 recurrence gemm (Bf2 x h1_old) hoisted BEFORE epi0 so the
//      epilogue (MUFU) overlaps tensor work of other warps
//  (c) strength-reduced addressing in the hgemm hot loop.

#define BATCH  4096
#define TLEN   128
#define OUTLEN 64
#define HID    200
#define MCTA   32
#define NTHR   640
#define NBLK   128
#define KSTEPS 13            // 13*16 = 208 >= 200 (zero padded)
#define NTILES 100           // 800 / 8
#define FRAG_ELEMS (KSTEPS * NTILES * 32)
#define ASTR   216           // A row stride in bf16 elems (432 B)
#define ABUF_B (32 * ASTR * 2)   // 13824 bytes per A buffer

typedef unsigned int u32;

// B fragments, per matrix: [s][jt][lane] -> uint4 {Bhi k01, Bhi k89, Blo k01, Blo k89}.
// 0=enc_Whh0 1=enc_Wih1 2=enc_Whh1 3=dec_Whh0 4=dec_Wih1 5=dec_Whh1
__device__ uint4 g_Bf[6][FRAG_ELEMS];
// vectors indexed by col n = u*4+g: 0=enc_Wih0 1=enc_b0 2=enc_b1 3=dec_Wih0 4=dec_b0 5=dec_b1
__device__ float g_v[6][800];

__device__ __forceinline__ void bsplit(float w, u32& hi, u32& lo) {
    __nv_bfloat16 h = __float2bfloat16(w);
    __nv_bfloat16 l = __float2bfloat16(w - __bfloat162float(h));
    hi = (u32)__bfloat16_as_ushort(h);
    lo = (u32)__bfloat16_as_ushort(l);
}

__global__ void prep_kernel(const float* __restrict__ eWhh0, const float* __restrict__ eWih1,
                            const float* __restrict__ eWhh1, const float* __restrict__ dWhh0,
                            const float* __restrict__ dWih1, const float* __restrict__ dWhh1,
                            const float* __restrict__ eWih0, const float* __restrict__ eb0,
                            const float* __restrict__ eb1,  const float* __restrict__ dWih0,
                            const float* __restrict__ db0,  const float* __restrict__ db1)
{
    int idx = blockIdx.x * blockDim.x + threadIdx.x;
    if (idx < FRAG_ELEMS) {
        int lane = idx & 31;
        int sj   = idx >> 5;
        int jt   = sj % NTILES;
        int s    = sj / NTILES;
        int gid  = lane >> 2, tig = lane & 3;
        int n = jt * 8 + gid;
        int u = n >> 2, g = n & 3;
        int R = g * HID + u;
        int k0 = s * 16 + tig * 2;
        const float* srcs[6] = {eWhh0, eWih1, eWhh1, dWhh0, dWih1, dWhh1};
#pragma unroll
        for (int m = 0; m < 6; m++) {
            const float* src = srcs[m] + R * HID;
            float w00 = (k0     < HID) ? src[k0]     : 0.f;
            float w01 = (k0 + 1 < HID) ? src[k0 + 1] : 0.f;
            float w10 = (k0 + 8 < HID) ? src[k0 + 8] : 0.f;
            float w11 = (k0 + 9 < HID) ? src[k0 + 9] : 0.f;
            u32 h00, l00, h01, l01, h10, l10, h11, l11;
            bsplit(w00, h00, l00); bsplit(w01, h01, l01);
            bsplit(w10, h10, l10); bsplit(w11, h11, l11);
            uint4 v;
            v.x = h00 | (h01 << 16);
            v.y = h10 | (h11 << 16);
            v.z = l00 | (l01 << 16);
            v.w = l10 | (l11 << 16);
            g_Bf[m][idx] = v;
        }
    }
    if (idx < 800) {
        int u = idx >> 2, g = idx & 3;
        int sI = g * HID + u;
        g_v[0][idx] = eWih0[sI];
        g_v[1][idx] = eb0[sI];
        g_v[2][idx] = eb1[sI];
        g_v[3][idx] = dWih0[sI];
        g_v[4][idx] = db0[sI];
        g_v[5][idx] = db1[sI];
    }
}

// ---- device primitives ----
__device__ __forceinline__ u32 smem_u32(const void* p) {
    u32 a;
    asm("{ .reg .u64 t; cvta.to.shared.u64 t, %1; cvt.u32.u64 %0, t; }" : "=r"(a) : "l"(p));
    return a;
}
__device__ __forceinline__ void ldsm4(u32 (&d)[4], u32 addr) {
    asm volatile("ldmatrix.sync.aligned.m8n8.x4.shared.b16 {%0,%1,%2,%3}, [%4];"
                 : "=r"(d[0]), "=r"(d[1]), "=r"(d[2]), "=r"(d[3]) : "r"(addr));
}
__device__ __forceinline__ void mma16816(float (&c)[4], const u32 (&a)[4], u32 b0, u32 b1) {
    asm volatile("mma.sync.aligned.m16n8k16.row.col.f32.bf16.bf16.f32 "
                 "{%0,%1,%2,%3},{%4,%5,%6,%7},{%8,%9},{%0,%1,%2,%3};"
                 : "+f"(c[0]), "+f"(c[1]), "+f"(c[2]), "+f"(c[3])
                 : "r"(a[0]), "r"(a[1]), "r"(a[2]), "r"(a[3]), "r"(b0), "r"(b1));
}
__device__ __forceinline__ float sigf(float x)   { return __fdividef(1.f, 1.f + __expf(-x)); }
__device__ __forceinline__ float tanh_f(float x) { return 1.f - __fdividef(2.f, 1.f + __expf(2.f * x)); }

// gates += (Ahi+Alo) @ (Bhi+Blo)^T (dropping Alo*Blo). aHi/aLo = per-lane smem
// byte addrs (mtile 1 at +16*432B). Strength-reduced pointers.
__device__ __forceinline__ void hgemm(const uint4* __restrict__ Bf, u32 aHi, u32 aLo,
                                      int w5, int lane, float (&acc)[2][5][4])
{
    const uint4* __restrict__ bp = Bf + w5 * 32 + lane;
#pragma unroll 1
    for (int s = 0; s < KSTEPS; s++) {
        u32 ah[2][4], al[2][4];
        ldsm4(ah[0], aHi);
        ldsm4(ah[1], aHi + 16 * 432);
        ldsm4(al[0], aLo);
        ldsm4(al[1], aLo + 16 * 432);
        aHi += 32; aLo += 32;
#pragma unroll
        for (int j = 0; j < 5; j++) {
            uint4 b = bp[j * 32];
            mma16816(acc[0][j], ah[0], b.x, b.y);
            mma16816(acc[1][j], ah[1], b.x, b.y);
            mma16816(acc[0][j], al[0], b.x, b.y);
            mma16816(acc[1][j], al[1], b.x, b.y);
            mma16816(acc[0][j], ah[0], b.z, b.w);
            mma16816(acc[1][j], ah[1], b.z, b.w);
        }
        bp += NTILES * 32;
    }
}

// acc init: bias + (optional) rank-1 wx * x[row].
__device__ __forceinline__ void acc_init(float (&acc)[2][5][4], const float* __restrict__ bias,
                                         const float* __restrict__ wx, const float* __restrict__ xrow,
                                         int w5, int lane)
{
    int gid = lane >> 2, tig = lane & 3;
#pragma unroll
    for (int mt = 0; mt < 2; mt++) {
        float xa = 0.f, xb = 0.f;
        if (xrow) { xa = xrow[mt * 16 + gid]; xb = xrow[mt * 16 + gid + 8]; }
#pragma unroll
        for (int j = 0; j < 5; j++) {
            int col0 = (w5 + j) * 8 + tig * 2;
            float b0v = bias[col0], b1v = bias[col0 + 1];
            if (xrow) {
                float w0 = wx[col0], w1 = wx[col0 + 1];
                acc[mt][j][0] = b0v + w0 * xa;
                acc[mt][j][1] = b1v + w1 * xa;
                acc[mt][j][2] = b0v + w0 * xb;
                acc[mt][j][3] = b1v + w1 * xb;
            } else {
                acc[mt][j][0] = b0v; acc[mt][j][1] = b1v;
                acc[mt][j][2] = b0v; acc[mt][j][3] = b1v;
            }
        }
    }
}

// Cell epilogue: even tig holds (i,f), odd (g,o) of the same unit; shfl_xor(1).
// Writes c (fp32, owner-only) and h bf16 hi/lo into the NEXT A buffers.
__device__ __forceinline__ void cell_epi(float (&acc)[2][5][4], float* __restrict__ cs,
                                         __nv_bfloat16* __restrict__ Ahi,
                                         __nv_bfloat16* __restrict__ Alo,
                                         int w5, int lane)
{
    int gid = lane >> 2, tig = lane & 3;
    bool ev = !(tig & 1);
#pragma unroll
    for (int mt = 0; mt < 2; mt++) {
#pragma unroll
        for (int j = 0; j < 5; j++) {
            int u = 2 * (w5 + j) + (tig >> 1);
            float o0 = __shfl_xor_sync(0xffffffffu, acc[mt][j][0], 1);
            float o1 = __shfl_xor_sync(0xffffffffu, acc[mt][j][1], 1);
            float o2 = __shfl_xor_sync(0xffffffffu, acc[mt][j][2], 1);
            float o3 = __shfl_xor_sync(0xffffffffu, acc[mt][j][3], 1);
            float gi, gf, gg, go;
            int row;
            if (ev) { gi = acc[mt][j][0]; gf = acc[mt][j][1]; gg = o0; go = o1; row = mt * 16 + gid; }
            else    { gi = o2; gf = o3; gg = acc[mt][j][2]; go = acc[mt][j][3]; row = mt * 16 + gid + 8; }
            float cv = cs[u * 32 + row];
            float cn = sigf(gf) * cv + sigf(gi) * tanh_f(gg);
            cs[u * 32 + row] = cn;
            float h = sigf(go) * tanh_f(cn);
            __nv_bfloat16 hh = __float2bfloat16(h);
            Ahi[row * ASTR + u] = hh;
            Alo[row * ASTR + u] = __float2bfloat16(h - __bfloat162float(hh));
        }
    }
}

// smem floats: Abufs 8*13824B = 27648 | c0 6400 | c1 6400 | xs 4096 | vb 4800 |
//              lin 200 | inp 32 | part 256  = 49832 floats (199,328 B)
#define SMEM_FLOATS 49832

__global__ void __launch_bounds__(NTHR, 1)
lstm_kernel(const float* __restrict__ x, const float* __restrict__ linW,
            const float* __restrict__ linb, float* __restrict__ out)
{
    extern __shared__ float sm[];
    char* ab = reinterpret_cast<char*>(sm);
    // A buffers (bf16, ABUF_B each): [0,1]=h0hi buf0/1, [2,3]=h0lo, [4,5]=h1hi, [6,7]=h1lo
    float* c0s   = sm + 27648;
    float* c1s   = sm + 34048;
    float* xs    = sm + 40448;    // [t=128][row=32]
    float* vb    = sm + 44544;    // 6 x 800
    float* lin_s = sm + 49344;    // 200
    float* inp_s = sm + 49544;    // 32
    float* part  = sm + 49576;    // 8 x 32

    const int tid  = threadIdx.x;
    const int lane = tid & 31;
    const int w5   = (tid >> 5) * 5;
    const int row0 = blockIdx.x * MCTA;

    // ldmatrix per-lane base offset within an A buffer
    const int blk = lane >> 3, rr = lane & 7;
    const u32 aoff = (u32)(((blk & 1) * 8 + rr) * 432 + (blk >> 1) * 16);
    const u32 abase = smem_u32(ab) + aoff;

    // zero A buffers + c states; stage xs, vb, lin
    for (int i = tid; i < 40448; i += NTHR) sm[i] = 0.f;
    for (int i = tid; i < TLEN * MCTA; i += NTHR) {
        int t = i >> 5, r = i & 31;
        xs[i] = x[(row0 + r) * TLEN + t];
    }
    {
        const float* gv = &g_v[0][0];
        for (int i = tid; i < 6 * 800; i += NTHR) vb[i] = gv[i];
    }
    for (int i = tid; i < HID; i += NTHR) lin_s[i] = linW[i];
    __syncthreads();

    const float* wx0  = vb;
    const float* b0   = vb + 800;
    const float* b1   = vb + 1600;
    const float* dwx0 = vb + 2400;
    const float* db0  = vb + 3200;
    const float* db1  = vb + 4000;

    int cur = 0;

    // ---------------- encoder: 128 steps, 2 syncs each ----------------
    for (int t = 0; t < TLEN; t++) {
        const int nxt = cur ^ 1;
        const u32 aH0c = abase + (u32)(cur * ABUF_B);
        const u32 aL0c = abase + (u32)((2 + cur) * ABUF_B);
        const u32 aH1c = abase + (u32)((4 + cur) * ABUF_B);
        const u32 aL1c = abase + (u32)((6 + cur) * ABUF_B);
        const u32 aH0n = abase + (u32)(nxt * ABUF_B);
        const u32 aL0n = abase + (u32)((2 + nxt) * ABUF_B);
        __nv_bfloat16* H0h = reinterpret_cast<__nv_bfloat16*>(ab + nxt * ABUF_B);
        __nv_bfloat16* H0l = reinterpret_cast<__nv_bfloat16*>(ab + (2 + nxt) * ABUF_B);
        __nv_bfloat16* H1h = reinterpret_cast<__nv_bfloat16*>(ab + (4 + nxt) * ABUF_B);
        __nv_bfloat16* H1l = reinterpret_cast<__nv_bfloat16*>(ab + (6 + nxt) * ABUF_B);

        float acc0[2][5][4];
        acc_init(acc0, b0, wx0, xs + t * 32, w5, lane);
        hgemm(g_Bf[0], aH0c, aL0c, w5, lane, acc0);          // recurrence h0_old

        float acc1[2][5][4];
        acc_init(acc1, b1, (const float*)0, (const float*)0, w5, lane);
        hgemm(g_Bf[2], aH1c, aL1c, w5, lane, acc1);          // recurrence h1_old (independent)

        cell_epi(acc0, c0s, H0h, H0l, w5, lane);             // write h0_new (nxt buf) - overlaps
        __syncthreads();                                     // all epi0 done

        hgemm(g_Bf[1], aH0n, aL0n, w5, lane, acc1);          // input = h0_new
        cell_epi(acc1, c1s, H1h, H1l, w5, lane);
        __syncthreads();                                     // all epi1 done
        cur = nxt;
    }

    // decoder initial input = x[:, T-1]
    if (tid < MCTA) inp_s[tid] = xs[(TLEN - 1) * 32 + tid];
    __syncthreads();

    const float lb = linb[0];

    // ---------------- decoder: 64 steps ----------------
    for (int t = 0; t < OUTLEN; t++) {
        const int nxt = cur ^ 1;
        const u32 aH0c = abase + (u32)(cur * ABUF_B);
        const u32 aL0c = abase + (u32)((2 + cur) * ABUF_B);
        const u32 aH1c = abase + (u32)((4 + cur) * ABUF_B);
        const u32 aL1c = abase + (u32)((6 + cur) * ABUF_B);
        const u32 aH0n = abase + (u32)(nxt * ABUF_B);
        const u32 aL0n = abase + (u32)((2 + nxt) * ABUF_B);
        __nv_bfloat16* H0h = reinterpret_cast<__nv_bfloat16*>(ab + nxt * ABUF_B);
        __nv_bfloat16* H0l = reinterpret_cast<__nv_bfloat16*>(ab + (2 + nxt) * ABUF_B);
        __nv_bfloat16* H1h = reinterpret_cast<__nv_bfloat16*>(ab + (4 + nxt) * ABUF_B);
        __nv_bfloat16* H1l = reinterpret_cast<__nv_bfloat16*>(ab + (6 + nxt) * ABUF_B);

        float acc0[2][5][4];
        acc_init(acc0, db0, dwx0, inp_s, w5, lane);
        hgemm(g_Bf[3], aH0c, aL0c, w5, lane, acc0);

        float acc1[2][5][4];
        acc_init(acc1, db1, (const float*)0, (const float*)0, w5, lane);
        hgemm(g_Bf[5], aH1c, aL1c, w5, lane, acc1);          // h1 recurrence (independent)

        cell_epi(acc0, c0s, H0h, H0l, w5, lane);
        __syncthreads();

        hgemm(g_Bf[4], aH0n, aL0n, w5, lane, acc1);          // input = h0_new
        cell_epi(acc1, c1s, H1h, H1l, w5, lane);
        __syncthreads();

        // linear head on h1_new (hi+lo), 8 groups x 25 units
        if (tid < 256) {
            int grp = tid >> 5, r = tid & 31;
            int ub = grp * 25;
            float s = 0.f;
#pragma unroll 5
            for (int u = 0; u < 25; u++) {
                int uu = ub + u;
                float hv = __bfloat162float(H1h[r * ASTR + uu]) +
                           __bfloat162float(H1l[r * ASTR + uu]);
                s += lin_s[uu] * hv;
            }
            part[grp * 32 + r] = s;
        }
        __syncthreads();
        if (tid < MCTA) {
            float s = lb;
#pragma unroll
            for (int g = 0; g < 8; g++) s += part[g * 32 + tid];
            out[(row0 + tid) * OUTLEN + t] = s;
            inp_s[tid] = s;
        }
        __syncthreads();
        cur = nxt;
    }
}

extern "C" void kernel_launch(void* const* d_in, const int* in_sizes, int n_in,
                              void* d_out, int out_size)
{
    (void)in_sizes; (void)n_in; (void)out_size;
    const float* x     = (const float*)d_in[0];
    const float* eWih0 = (const float*)d_in[1];
    const float* eWhh0 = (const float*)d_in[2];
    const float* eb0   = (const float*)d_in[3];
    const float* eWih1 = (const float*)d_in[4];
    const float* eWhh1 = (const float*)d_in[5];
    const float* eb1   = (const float*)d_in[6];
    const float* dWih0 = (const float*)d_in[7];
    const float* dWhh0 = (const float*)d_in[8];
    const float* db0   = (const float*)d_in[9];
    const float* dWih1 = (const float*)d_in[10];
    const float* dWhh1 = (const float*)d_in[11];
    const float* db1   = (const float*)d_in[12];
    const float* linW  = (const float*)d_in[13];
    const float* linb  = (const float*)d_in[14];
    float* out = (float*)d_out;

    cudaFuncSetAttribute(lstm_kernel, cudaFuncAttributeMaxDynamicSharedMemorySize,
                         SMEM_FLOATS * (int)sizeof(float));

    prep_kernel<<<(FRAG_ELEMS + 255) / 256, 256>>>(eWhh0, eWih1, eWhh1, dWhh0, dWih1, dWhh1,
                                                   eWih0, eb0, eb1, dWih0, db0, db1);
    lstm_kernel<<<NBLK, NTHR, SMEM_FLOATS * (int)sizeof(float)>>>(x, linW, linb, out);
}

// round 14
// speedup vs baseline: 1.2659x; 1.2659x over previous
#include <cuda_runtime.h>
#include <cuda_bf16.h>

// LSTMForecastModel: B=4096, T=128, OUT=64, H=200.
// R13 = R11 mma core (m16n8k16 bf16x3 split, fp32 accum, ONE live accumulator)
//  + double-buffered h A-buffers -> 2 syncthreads/step (R12's win, without its
//    concurrent-accumulator register spills)
//  + per-kstep B fragment loads batched up front (MLP=5 vs L2 latency).

#define BATCH  4096
#define TLEN   128
#define OUTLEN 64
#define HID    200
#define MCTA   32
#define NTHR   640
#define NBLK   128
#define KSTEPS 13            // 13*16 = 208 >= 200 (zero padded)
#define NTILES 100           // 800 / 8
#define FRAG_ELEMS (KSTEPS * NTILES * 32)
#define ASTR   216           // A row stride in bf16 elems (432 B)
#define ABUF_B (32 * ASTR * 2)   // 13824 bytes per A buffer

typedef unsigned int u32;

// B fragments, per matrix: [s][jt][lane] -> uint4 {Bhi k01, Bhi k89, Blo k01, Blo k89}.
// 0=enc_Whh0 1=enc_Wih1 2=enc_Whh1 3=dec_Whh0 4=dec_Wih1 5=dec_Whh1
__device__ uint4 g_Bf[6][FRAG_ELEMS];
// vectors indexed by col n = u*4+g: 0=enc_Wih0 1=enc_b0 2=enc_b1 3=dec_Wih0 4=dec_b0 5=dec_b1
__device__ float g_v[6][800];

__device__ __forceinline__ void bsplit(float w, u32& hi, u32& lo) {
    __nv_bfloat16 h = __float2bfloat16(w);
    __nv_bfloat16 l = __float2bfloat16(w - __bfloat162float(h));
    hi = (u32)__bfloat16_as_ushort(h);
    lo = (u32)__bfloat16_as_ushort(l);
}

__global__ void prep_kernel(const float* __restrict__ eWhh0, const float* __restrict__ eWih1,
                            const float* __restrict__ eWhh1, const float* __restrict__ dWhh0,
                            const float* __restrict__ dWih1, const float* __restrict__ dWhh1,
                            const float* __restrict__ eWih0, const float* __restrict__ eb0,
                            const float* __restrict__ eb1,  const float* __restrict__ dWih0,
                            const float* __restrict__ db0,  const float* __restrict__ db1)
{
    int idx = blockIdx.x * blockDim.x + threadIdx.x;
    if (idx < FRAG_ELEMS) {
        int lane = idx & 31;
        int sj   = idx >> 5;
        int jt   = sj % NTILES;
        int s    = sj / NTILES;
        int gid  = lane >> 2, tig = lane & 3;
        int n = jt * 8 + gid;
        int u = n >> 2, g = n & 3;
        int R = g * HID + u;
        int k0 = s * 16 + tig * 2;
        const float* srcs[6] = {eWhh0, eWih1, eWhh1, dWhh0, dWih1, dWhh1};
#pragma unroll
        for (int m = 0; m < 6; m++) {
            const float* src = srcs[m] + R * HID;
            float w00 = (k0     < HID) ? src[k0]     : 0.f;
            float w01 = (k0 + 1 < HID) ? src[k0 + 1] : 0.f;
            float w10 = (k0 + 8 < HID) ? src[k0 + 8] : 0.f;
            float w11 = (k0 + 9 < HID) ? src[k0 + 9] : 0.f;
            u32 h00, l00, h01, l01, h10, l10, h11, l11;
            bsplit(w00, h00, l00); bsplit(w01, h01, l01);
            bsplit(w10, h10, l10); bsplit(w11, h11, l11);
            uint4 v;
            v.x = h00 | (h01 << 16);
            v.y = h10 | (h11 << 16);
            v.z = l00 | (l01 << 16);
            v.w = l10 | (l11 << 16);
            g_Bf[m][idx] = v;
        }
    }
    if (idx < 800) {
        int u = idx >> 2, g = idx & 3;
        int sI = g * HID + u;
        g_v[0][idx] = eWih0[sI];
        g_v[1][idx] = eb0[sI];
        g_v[2][idx] = eb1[sI];
        g_v[3][idx] = dWih0[sI];
        g_v[4][idx] = db0[sI];
        g_v[5][idx] = db1[sI];
    }
}

// ---- device primitives ----
__device__ __forceinline__ u32 smem_u32(const void* p) {
    u32 a;
    asm("{ .reg .u64 t; cvta.to.shared.u64 t, %1; cvt.u32.u64 %0, t; }" : "=r"(a) : "l"(p));
    return a;
}
__device__ __forceinline__ void ldsm4(u32 (&d)[4], u32 addr) {
    asm volatile("ldmatrix.sync.aligned.m8n8.x4.shared.b16 {%0,%1,%2,%3}, [%4];"
                 : "=r"(d[0]), "=r"(d[1]), "=r"(d[2]), "=r"(d[3]) : "r"(addr));
}
__device__ __forceinline__ void mma16816(float (&c)[4], const u32 (&a)[4], u32 b0, u32 b1) {
    asm volatile("mma.sync.aligned.m16n8k16.row.col.f32.bf16.bf16.f32 "
                 "{%0,%1,%2,%3},{%4,%5,%6,%7},{%8,%9},{%0,%1,%2,%3};"
                 : "+f"(c[0]), "+f"(c[1]), "+f"(c[2]), "+f"(c[3])
                 : "r"(a[0]), "r"(a[1]), "r"(a[2]), "r"(a[3]), "r"(b0), "r"(b1));
}
__device__ __forceinline__ float sigf(float x)   { return __fdividef(1.f, 1.f + __expf(-x)); }
__device__ __forceinline__ float tanh_f(float x) { return 1.f - __fdividef(2.f, 1.f + __expf(2.f * x)); }

// gates += (Ahi+Alo) @ (Bhi+Blo)^T (dropping Alo*Blo).
// Per kstep: 5 B LDG.128 issued up front (MLP=5), then 4 ldsm, then 30 mmas.
__device__ __forceinline__ void hgemm(const uint4* __restrict__ Bf, u32 aHi, u32 aLo,
                                      int w5, int lane, float (&acc)[2][5][4])
{
    const uint4* __restrict__ bp = Bf + w5 * 32 + lane;
#pragma unroll 1
    for (int s = 0; s < KSTEPS; s++) {
        uint4 b0 = bp[0];
        uint4 b1 = bp[32];
        uint4 b2 = bp[64];
        uint4 b3 = bp[96];
        uint4 b4 = bp[128];
        u32 ah[2][4], al[2][4];
        ldsm4(ah[0], aHi);
        ldsm4(ah[1], aHi + 16 * 432);
        ldsm4(al[0], aLo);
        ldsm4(al[1], aLo + 16 * 432);
        aHi += 32; aLo += 32;

        mma16816(acc[0][0], ah[0], b0.x, b0.y);
        mma16816(acc[1][0], ah[1], b0.x, b0.y);
        mma16816(acc[0][0], al[0], b0.x, b0.y);
        mma16816(acc[1][0], al[1], b0.x, b0.y);
        mma16816(acc[0][0], ah[0], b0.z, b0.w);
        mma16816(acc[1][0], ah[1], b0.z, b0.w);

        mma16816(acc[0][1], ah[0], b1.x, b1.y);
        mma16816(acc[1][1], ah[1], b1.x, b1.y);
        mma16816(acc[0][1], al[0], b1.x, b1.y);
        mma16816(acc[1][1], al[1], b1.x, b1.y);
        mma16816(acc[0][1], ah[0], b1.z, b1.w);
        mma16816(acc[1][1], ah[1], b1.z, b1.w);

        mma16816(acc[0][2], ah[0], b2.x, b2.y);
        mma16816(acc[1][2], ah[1], b2.x, b2.y);
        mma16816(acc[0][2], al[0], b2.x, b2.y);
        mma16816(acc[1][2], al[1], b2.x, b2.y);
        mma16816(acc[0][2], ah[0], b2.z, b2.w);
        mma16816(acc[1][2], ah[1], b2.z, b2.w);

        mma16816(acc[0][3], ah[0], b3.x, b3.y);
        mma16816(acc[1][3], ah[1], b3.x, b3.y);
        mma16816(acc[0][3], al[0], b3.x, b3.y);
        mma16816(acc[1][3], al[1], b3.x, b3.y);
        mma16816(acc[0][3], ah[0], b3.z, b3.w);
        mma16816(acc[1][3], ah[1], b3.z, b3.w);

        mma16816(acc[0][4], ah[0], b4.x, b4.y);
        mma16816(acc[1][4], ah[1], b4.x, b4.y);
        mma16816(acc[0][4], al[0], b4.x, b4.y);
        mma16816(acc[1][4], al[1], b4.x, b4.y);
        mma16816(acc[0][4], ah[0], b4.z, b4.w);
        mma16816(acc[1][4], ah[1], b4.z, b4.w);

        bp += NTILES * 32;
    }
}

// acc init: bias + (optional) rank-1 wx * x[row].
__device__ __forceinline__ void acc_init(float (&acc)[2][5][4], const float* __restrict__ bias,
                                         const float* __restrict__ wx, const float* __restrict__ xrow,
                                         int w5, int lane)
{
    int gid = lane >> 2, tig = lane & 3;
#pragma unroll
    for (int mt = 0; mt < 2; mt++) {
        float xa = 0.f, xb = 0.f;
        if (xrow) { xa = xrow[mt * 16 + gid]; xb = xrow[mt * 16 + gid + 8]; }
#pragma unroll
        for (int j = 0; j < 5; j++) {
            int col0 = (w5 + j) * 8 + tig * 2;
            float b0v = bias[col0], b1v = bias[col0 + 1];
            if (xrow) {
                float w0 = wx[col0], w1 = wx[col0 + 1];
                acc[mt][j][0] = b0v + w0 * xa;
                acc[mt][j][1] = b1v + w1 * xa;
                acc[mt][j][2] = b0v + w0 * xb;
                acc[mt][j][3] = b1v + w1 * xb;
            } else {
                acc[mt][j][0] = b0v; acc[mt][j][1] = b1v;
                acc[mt][j][2] = b0v; acc[mt][j][3] = b1v;
            }
        }
    }
}

// Cell epilogue: even tig holds (i,f), odd (g,o) of the same unit; shfl_xor(1).
// Writes c (fp32, owner-only) and h bf16 hi/lo into the NEXT A buffers.
__device__ __forceinline__ void cell_epi(float (&acc)[2][5][4], float* __restrict__ cs,
                                         __nv_bfloat16* __restrict__ Ahi,
                                         __nv_bfloat16* __restrict__ Alo,
                                         int w5, int lane)
{
    int gid = lane >> 2, tig = lane & 3;
    bool ev = !(tig & 1);
#pragma unroll
    for (int mt = 0; mt < 2; mt++) {
#pragma unroll
        for (int j = 0; j < 5; j++) {
            int u = 2 * (w5 + j) + (tig >> 1);
            float o0 = __shfl_xor_sync(0xffffffffu, acc[mt][j][0], 1);
            float o1 = __shfl_xor_sync(0xffffffffu, acc[mt][j][1], 1);
            float o2 = __shfl_xor_sync(0xffffffffu, acc[mt][j][2], 1);
            float o3 = __shfl_xor_sync(0xffffffffu, acc[mt][j][3], 1);
            float gi, gf, gg, go;
            int row;
            if (ev) { gi = acc[mt][j][0]; gf = acc[mt][j][1]; gg = o0; go = o1; row = mt * 16 + gid; }
            else    { gi = o2; gf = o3; gg = acc[mt][j][2]; go = acc[mt][j][3]; row = mt * 16 + gid + 8; }
            float cv = cs[u * 32 + row];
            float cn = sigf(gf) * cv + sigf(gi) * tanh_f(gg);
            cs[u * 32 + row] = cn;
            float h = sigf(go) * tanh_f(cn);
            __nv_bfloat16 hh = __float2bfloat16(h);
            Ahi[row * ASTR + u] = hh;
            Alo[row * ASTR + u] = __float2bfloat16(h - __bfloat162float(hh));
        }
    }
}

// smem floats: Abufs 8*13824B = 27648 | c0 6400 | c1 6400 | xs 4096 | vb 4800 |
//              lin 200 | inp 32 | part 256  = 49832 floats (199,328 B)
#define SMEM_FLOATS 49832

__global__ void __launch_bounds__(NTHR, 1)
lstm_kernel(const float* __restrict__ x, const float* __restrict__ linW,
            const float* __restrict__ linb, float* __restrict__ out)
{
    extern __shared__ float sm[];
    char* ab = reinterpret_cast<char*>(sm);
    // A buffers (bf16, ABUF_B each): [0,1]=h0hi buf0/1, [2,3]=h0lo, [4,5]=h1hi, [6,7]=h1lo
    float* c0s   = sm + 27648;
    float* c1s   = sm + 34048;
    float* xs    = sm + 40448;    // [t=128][row=32]
    float* vb    = sm + 44544;    // 6 x 800
    float* lin_s = sm + 49344;    // 200
    float* inp_s = sm + 49544;    // 32
    float* part  = sm + 49576;    // 8 x 32

    const int tid  = threadIdx.x;
    const int lane = tid & 31;
    const int w5   = (tid >> 5) * 5;
    const int row0 = blockIdx.x * MCTA;

    // ldmatrix per-lane base offset within an A buffer
    const int blk = lane >> 3, rr = lane & 7;
    const u32 aoff = (u32)(((blk & 1) * 8 + rr) * 432 + (blk >> 1) * 16);
    const u32 abase = smem_u32(ab) + aoff;

    // zero A buffers + c states; stage xs, vb, lin
    for (int i = tid; i < 40448; i += NTHR) sm[i] = 0.f;
    for (int i = tid; i < TLEN * MCTA; i += NTHR) {
        int t = i >> 5, r = i & 31;
        xs[i] = x[(row0 + r) * TLEN + t];
    }
    {
        const float* gv = &g_v[0][0];
        for (int i = tid; i < 6 * 800; i += NTHR) vb[i] = gv[i];
    }
    for (int i = tid; i < HID; i += NTHR) lin_s[i] = linW[i];
    __syncthreads();

    const float* wx0  = vb;
    const float* b0   = vb + 800;
    const float* b1   = vb + 1600;
    const float* dwx0 = vb + 2400;
    const float* db0  = vb + 3200;
    const float* db1  = vb + 4000;

    int cur = 0;

    // ---------------- encoder: 128 steps, 2 syncs each, ONE live acc ----------------
    for (int t = 0; t < TLEN; t++) {
        const int nxt = cur ^ 1;
        const u32 aH0c = abase + (u32)(cur * ABUF_B);
        const u32 aL0c = abase + (u32)((2 + cur) * ABUF_B);
        const u32 aH1c = abase + (u32)((4 + cur) * ABUF_B);
        const u32 aL1c = abase + (u32)((6 + cur) * ABUF_B);
        const u32 aH0n = abase + (u32)(nxt * ABUF_B);
        const u32 aL0n = abase + (u32)((2 + nxt) * ABUF_B);
        __nv_bfloat16* H0h = reinterpret_cast<__nv_bfloat16*>(ab + nxt * ABUF_B);
        __nv_bfloat16* H0l = reinterpret_cast<__nv_bfloat16*>(ab + (2 + nxt) * ABUF_B);
        __nv_bfloat16* H1h = reinterpret_cast<__nv_bfloat16*>(ab + (4 + nxt) * ABUF_B);
        __nv_bfloat16* H1l = reinterpret_cast<__nv_bfloat16*>(ab + (6 + nxt) * ABUF_B);

        {   // layer 0
            float acc[2][5][4];
            acc_init(acc, b0, wx0, xs + t * 32, w5, lane);
            hgemm(g_Bf[0], aH0c, aL0c, w5, lane, acc);       // recurrence h0_old
            cell_epi(acc, c0s, H0h, H0l, w5, lane);          // write h0_new (nxt buf)
        }
        __syncthreads();                                     // epi0 done

        {   // layer 1
            float acc[2][5][4];
            acc_init(acc, b1, (const float*)0, (const float*)0, w5, lane);
            hgemm(g_Bf[1], aH0n, aL0n, w5, lane, acc);       // input = h0_new
            hgemm(g_Bf[2], aH1c, aL1c, w5, lane, acc);       // recurrence h1_old
            cell_epi(acc, c1s, H1h, H1l, w5, lane);
        }
        __syncthreads();                                     // epi1 done
        cur = nxt;
    }

    // decoder initial input = x[:, T-1]
    if (tid < MCTA) inp_s[tid] = xs[(TLEN - 1) * 32 + tid];
    __syncthreads();

    const float lb = linb[0];

    // ---------------- decoder: 64 steps ----------------
    for (int t = 0; t < OUTLEN; t++) {
        const int nxt = cur ^ 1;
        const u32 aH0c = abase + (u32)(cur * ABUF_B);
        const u32 aL0c = abase + (u32)((2 + cur) * ABUF_B);
        const u32 aH1c = abase + (u32)((4 + cur) * ABUF_B);
        const u32 aL1c = abase + (u32)((6 + cur) * ABUF_B);
        const u32 aH0n = abase + (u32)(nxt * ABUF_B);
        const u32 aL0n = abase + (u32)((2 + nxt) * ABUF_B);
        __nv_bfloat16* H0h = reinterpret_cast<__nv_bfloat16*>(ab + nxt * ABUF_B);
        __nv_bfloat16* H0l = reinterpret_cast<__nv_bfloat16*>(ab + (2 + nxt) * ABUF_B);
        __nv_bfloat16* H1h = reinterpret_cast<__nv_bfloat16*>(ab + (4 + nxt) * ABUF_B);
        __nv_bfloat16* H1l = reinterpret_cast<__nv_bfloat16*>(ab + (6 + nxt) * ABUF_B);

        {
            float acc[2][5][4];
            acc_init(acc, db0, dwx0, inp_s, w5, lane);
            hgemm(g_Bf[3], aH0c, aL0c, w5, lane, acc);
            cell_epi(acc, c0s, H0h, H0l, w5, lane);
        }
        __syncthreads();

        {
            float acc[2][5][4];
            acc_init(acc, db1, (const float*)0, (const float*)0, w5, lane);
            hgemm(g_Bf[4], aH0n, aL0n, w5, lane, acc);       // input = h0_new
            hgemm(g_Bf[5], aH1c, aL1c, w5, lane, acc);       // recurrence h1_old
            cell_epi(acc, c1s, H1h, H1l, w5, lane);
        }
        __syncthreads();

        // linear head on h1_new (hi+lo), 8 groups x 25 units
        if (tid < 256) {
            int grp = tid >> 5, r = tid & 31;
            int ub = grp * 25;
            float s = 0.f;
#pragma unroll 5
            for (int u = 0; u < 25; u++) {
                int uu = ub + u;
                float hv = __bfloat162float(H1h[r * ASTR + uu]) +
                           __bfloat162float(H1l[r * ASTR + uu]);
                s += lin_s[uu] * hv;
            }
            part[grp * 32 + r] = s;
        }
        __syncthreads();
        if (tid < MCTA) {
            float s = lb;
#pragma unroll
            for (int g = 0; g < 8; g++) s += part[g * 32 + tid];
            out[(row0 + tid) * OUTLEN + t] = s;
            inp_s[tid] = s;
        }
        __syncthreads();
        cur = nxt;
    }
}

extern "C" void kernel_launch(void* const* d_in, const int* in_sizes, int n_in,
                              void* d_out, int out_size)
{
    (void)in_sizes; (void)n_in; (void)out_size;
    const float* x     = (const float*)d_in[0];
    const float* eWih0 = (const float*)d_in[1];
    const float* eWhh0 = (const float*)d_in[2];
    const float* eb0   = (const float*)d_in[3];
    const float* eWih1 = (const float*)d_in[4];
    const float* eWhh1 = (const float*)d_in[5];
    const float* eb1   = (const float*)d_in[6];
    const float* dWih0 = (const float*)d_in[7];
    const float* dWhh0 = (const float*)d_in[8];
    const float* db0   = (const float*)d_in[9];
    const float* dWih1 = (const float*)d_in[10];
    const float* dWhh1 = (const float*)d_in[11];
    const float* db1   = (const float*)d_in[12];
    const float* linW  = (const float*)d_in[13];
    const float* linb  = (const float*)d_in[14];
    float* out = (float*)d_out;

    cudaFuncSetAttribute(lstm_kernel, cudaFuncAttributeMaxDynamicSharedMemorySize,
                         SMEM_FLOATS * (int)sizeof(float));

    prep_kernel<<<(FRAG_ELEMS + 255) / 256, 256>>>(eWhh0, eWih1, eWhh1, dWhh0, dWih1, dWhh1,
                                                   eWih0, eb0, eb1, dWih0, db0, db1);
    lstm_kernel<<<NBLK, NTHR, SMEM_FLOATS * (int)sizeof(float)>>>(x, linW, linb, out);
}

// round 15
// speedup vs baseline: 1.2701x; 1.0033x over previous
#include <cuda_runtime.h>
#include <cuda_bf16.h>

// LSTMForecastModel: B=4096, T=128, OUT=64, H=200.
// R14 = R13 mma core (m16n8k16 bf16x3 split, fp32 accum, one live acc, batched
// B loads) + RE-ORDERED encoder mainloop:
//   body(t) = [gemm1(t-1); epi1(t-1); gemm0(t); epi0(t); BAR]
// -> ONE __syncthreads per encoder step (was 2) and both cell epilogues sit
// between gemms, so their MUFU work overlaps other warps' tensor issue instead
// of draining the tensor pipe against a barrier.

#define BATCH  4096
#define TLEN   128
#define OUTLEN 64
#define HID    200
#define MCTA   32
#define NTHR   640
#define NBLK   128
#define KSTEPS 13            // 13*16 = 208 >= 200 (zero padded)
#define NTILES 100           // 800 / 8
#define FRAG_ELEMS (KSTEPS * NTILES * 32)
#define ASTR   216           // A row stride in bf16 elems (432 B)
#define ABUF_B (32 * ASTR * 2)   // 13824 bytes per A buffer

typedef unsigned int u32;

// B fragments, per matrix: [s][jt][lane] -> uint4 {Bhi k01, Bhi k89, Blo k01, Blo k89}.
// 0=enc_Whh0 1=enc_Wih1 2=enc_Whh1 3=dec_Whh0 4=dec_Wih1 5=dec_Whh1
__device__ uint4 g_Bf[6][FRAG_ELEMS];
// vectors indexed by col n = u*4+g: 0=enc_Wih0 1=enc_b0 2=enc_b1 3=dec_Wih0 4=dec_b0 5=dec_b1
__device__ float g_v[6][800];

__device__ __forceinline__ void bsplit(float w, u32& hi, u32& lo) {
    __nv_bfloat16 h = __float2bfloat16(w);
    __nv_bfloat16 l = __float2bfloat16(w - __bfloat162float(h));
    hi = (u32)__bfloat16_as_ushort(h);
    lo = (u32)__bfloat16_as_ushort(l);
}

__global__ void prep_kernel(const float* __restrict__ eWhh0, const float* __restrict__ eWih1,
                            const float* __restrict__ eWhh1, const float* __restrict__ dWhh0,
                            const float* __restrict__ dWih1, const float* __restrict__ dWhh1,
                            const float* __restrict__ eWih0, const float* __restrict__ eb0,
                            const float* __restrict__ eb1,  const float* __restrict__ dWih0,
                            const float* __restrict__ db0,  const float* __restrict__ db1)
{
    int idx = blockIdx.x * blockDim.x + threadIdx.x;
    if (idx < FRAG_ELEMS) {
        int lane = idx & 31;
        int sj   = idx >> 5;
        int jt   = sj % NTILES;
        int s    = sj / NTILES;
        int gid  = lane >> 2, tig = lane & 3;
        int n = jt * 8 + gid;
        int u = n >> 2, g = n & 3;
        int R = g * HID + u;
        int k0 = s * 16 + tig * 2;
        const float* srcs[6] = {eWhh0, eWih1, eWhh1, dWhh0, dWih1, dWhh1};
#pragma unroll
        for (int m = 0; m < 6; m++) {
            const float* src = srcs[m] + R * HID;
            float w00 = (k0     < HID) ? src[k0]     : 0.f;
            float w01 = (k0 + 1 < HID) ? src[k0 + 1] : 0.f;
            float w10 = (k0 + 8 < HID) ? src[k0 + 8] : 0.f;
            float w11 = (k0 + 9 < HID) ? src[k0 + 9] : 0.f;
            u32 h00, l00, h01, l01, h10, l10, h11, l11;
            bsplit(w00, h00, l00); bsplit(w01, h01, l01);
            bsplit(w10, h10, l10); bsplit(w11, h11, l11);
            uint4 v;
            v.x = h00 | (h01 << 16);
            v.y = h10 | (h11 << 16);
            v.z = l00 | (l01 << 16);
            v.w = l10 | (l11 << 16);
            g_Bf[m][idx] = v;
        }
    }
    if (idx < 800) {
        int u = idx >> 2, g = idx & 3;
        int sI = g * HID + u;
        g_v[0][idx] = eWih0[sI];
        g_v[1][idx] = eb0[sI];
        g_v[2][idx] = eb1[sI];
        g_v[3][idx] = dWih0[sI];
        g_v[4][idx] = db0[sI];
        g_v[5][idx] = db1[sI];
    }
}

// ---- device primitives ----
__device__ __forceinline__ u32 smem_u32(const void* p) {
    u32 a;
    asm("{ .reg .u64 t; cvta.to.shared.u64 t, %1; cvt.u32.u64 %0, t; }" : "=r"(a) : "l"(p));
    return a;
}
__device__ __forceinline__ void ldsm4(u32 (&d)[4], u32 addr) {
    asm volatile("ldmatrix.sync.aligned.m8n8.x4.shared.b16 {%0,%1,%2,%3}, [%4];"
                 : "=r"(d[0]), "=r"(d[1]), "=r"(d[2]), "=r"(d[3]) : "r"(addr));
}
__device__ __forceinline__ void mma16816(float (&c)[4], const u32 (&a)[4], u32 b0, u32 b1) {
    asm volatile("mma.sync.aligned.m16n8k16.row.col.f32.bf16.bf16.f32 "
                 "{%0,%1,%2,%3},{%4,%5,%6,%7},{%8,%9},{%0,%1,%2,%3};"
                 : "+f"(c[0]), "+f"(c[1]), "+f"(c[2]), "+f"(c[3])
                 : "r"(a[0]), "r"(a[1]), "r"(a[2]), "r"(a[3]), "r"(b0), "r"(b1));
}
__device__ __forceinline__ float sigf(float x)   { return __fdividef(1.f, 1.f + __expf(-x)); }
__device__ __forceinline__ float tanh_f(float x) { return 1.f - __fdividef(2.f, 1.f + __expf(2.f * x)); }

// gates += (Ahi+Alo) @ (Bhi+Blo)^T (dropping Alo*Blo).
// Per kstep: 5 B LDG.128 issued up front (MLP=5), then 4 ldsm, then 30 mmas.
__device__ __forceinline__ void hgemm(const uint4* __restrict__ Bf, u32 aHi, u32 aLo,
                                      int w5, int lane, float (&acc)[2][5][4])
{
    const uint4* __restrict__ bp = Bf + w5 * 32 + lane;
#pragma unroll 1
    for (int s = 0; s < KSTEPS; s++) {
        uint4 b0 = bp[0];
        uint4 b1 = bp[32];
        uint4 b2 = bp[64];
        uint4 b3 = bp[96];
        uint4 b4 = bp[128];
        u32 ah[2][4], al[2][4];
        ldsm4(ah[0], aHi);
        ldsm4(ah[1], aHi + 16 * 432);
        ldsm4(al[0], aLo);
        ldsm4(al[1], aLo + 16 * 432);
        aHi += 32; aLo += 32;

        mma16816(acc[0][0], ah[0], b0.x, b0.y);
        mma16816(acc[1][0], ah[1], b0.x, b0.y);
        mma16816(acc[0][0], al[0], b0.x, b0.y);
        mma16816(acc[1][0], al[1], b0.x, b0.y);
        mma16816(acc[0][0], ah[0], b0.z, b0.w);
        mma16816(acc[1][0], ah[1], b0.z, b0.w);

        mma16816(acc[0][1], ah[0], b1.x, b1.y);
        mma16816(acc[1][1], ah[1], b1.x, b1.y);
        mma16816(acc[0][1], al[0], b1.x, b1.y);
        mma16816(acc[1][1], al[1], b1.x, b1.y);
        mma16816(acc[0][1], ah[0], b1.z, b1.w);
        mma16816(acc[1][1], ah[1], b1.z, b1.w);

        mma16816(acc[0][2], ah[0], b2.x, b2.y);
        mma16816(acc[1][2], ah[1], b2.x, b2.y);
        mma16816(acc[0][2], al[0], b2.x, b2.y);
        mma16816(acc[1][2], al[1], b2.x, b2.y);
        mma16816(acc[0][2], ah[0], b2.z, b2.w);
        mma16816(acc[1][2], ah[1], b2.z, b2.w);

        mma16816(acc[0][3], ah[0], b3.x, b3.y);
        mma16816(acc[1][3], ah[1], b3.x, b3.y);
        mma16816(acc[0][3], al[0], b3.x, b3.y);
        mma16816(acc[1][3], al[1], b3.x, b3.y);
        mma16816(acc[0][3], ah[0], b3.z, b3.w);
        mma16816(acc[1][3], ah[1], b3.z, b3.w);

        mma16816(acc[0][4], ah[0], b4.x, b4.y);
        mma16816(acc[1][4], ah[1], b4.x, b4.y);
        mma16816(acc[0][4], al[0], b4.x, b4.y);
        mma16816(acc[1][4], al[1], b4.x, b4.y);
        mma16816(acc[0][4], ah[0], b4.z, b4.w);
        mma16816(acc[1][4], ah[1], b4.z, b4.w);

        bp += NTILES * 32;
    }
}

// acc init: bias + (optional) rank-1 wx * x[row].
__device__ __forceinline__ void acc_init(float (&acc)[2][5][4], const float* __restrict__ bias,
                                         const float* __restrict__ wx, const float* __restrict__ xrow,
                                         int w5, int lane)
{
    int gid = lane >> 2, tig = lane & 3;
#pragma unroll
    for (int mt = 0; mt < 2; mt++) {
        float xa = 0.f, xb = 0.f;
        if (xrow) { xa = xrow[mt * 16 + gid]; xb = xrow[mt * 16 + gid + 8]; }
#pragma unroll
        for (int j = 0; j < 5; j++) {
            int col0 = (w5 + j) * 8 + tig * 2;
            float b0v = bias[col0], b1v = bias[col0 + 1];
            if (xrow) {
                float w0 = wx[col0], w1 = wx[col0 + 1];
                acc[mt][j][0] = b0v + w0 * xa;
                acc[mt][j][1] = b1v + w1 * xa;
                acc[mt][j][2] = b0v + w0 * xb;
                acc[mt][j][3] = b1v + w1 * xb;
            } else {
                acc[mt][j][0] = b0v; acc[mt][j][1] = b1v;
                acc[mt][j][2] = b0v; acc[mt][j][3] = b1v;
            }
        }
    }
}

// Cell epilogue: even tig holds (i,f), odd (g,o) of the same unit; shfl_xor(1).
// Writes c (fp32, owner-only) and h bf16 hi/lo into the given A buffers.
__device__ __forceinline__ void cell_epi(float (&acc)[2][5][4], float* __restrict__ cs,
                                         __nv_bfloat16* __restrict__ Ahi,
                                         __nv_bfloat16* __restrict__ Alo,
                                         int w5, int lane)
{
    int gid = lane >> 2, tig = lane & 3;
    bool ev = !(tig & 1);
#pragma unroll
    for (int mt = 0; mt < 2; mt++) {
#pragma unroll
        for (int j = 0; j < 5; j++) {
            int u = 2 * (w5 + j) + (tig >> 1);
            float o0 = __shfl_xor_sync(0xffffffffu, acc[mt][j][0], 1);
            float o1 = __shfl_xor_sync(0xffffffffu, acc[mt][j][1], 1);
            float o2 = __shfl_xor_sync(0xffffffffu, acc[mt][j][2], 1);
            float o3 = __shfl_xor_sync(0xffffffffu, acc[mt][j][3], 1);
            float gi, gf, gg, go;
            int row;
            if (ev) { gi = acc[mt][j][0]; gf = acc[mt][j][1]; gg = o0; go = o1; row = mt * 16 + gid; }
            else    { gi = o2; gf = o3; gg = acc[mt][j][2]; go = acc[mt][j][3]; row = mt * 16 + gid + 8; }
            float cv = cs[u * 32 + row];
            float cn = sigf(gf) * cv + sigf(gi) * tanh_f(gg);
            cs[u * 32 + row] = cn;
            float h = sigf(go) * tanh_f(cn);
            __nv_bfloat16 hh = __float2bfloat16(h);
            Ahi[row * ASTR + u] = hh;
            Alo[row * ASTR + u] = __float2bfloat16(h - __bfloat162float(hh));
        }
    }
}

// smem floats: Abufs 8*13824B = 27648 | c0 6400 | c1 6400 | xs 4096 | vb 4800 |
//              lin 200 | inp 32 | part 256  = 49832 floats (199,328 B)
#define SMEM_FLOATS 49832

__global__ void __launch_bounds__(NTHR, 1)
lstm_kernel(const float* __restrict__ x, const float* __restrict__ linW,
            const float* __restrict__ linb, float* __restrict__ out)
{
    extern __shared__ float sm[];
    char* ab = reinterpret_cast<char*>(sm);
    // A buffers (bf16, ABUF_B each): [0,1]=h0hi buf0/1, [2,3]=h0lo, [4,5]=h1hi, [6,7]=h1lo
    float* c0s   = sm + 27648;
    float* c1s   = sm + 34048;
    float* xs    = sm + 40448;    // [t=128][row=32]
    float* vb    = sm + 44544;    // 6 x 800
    float* lin_s = sm + 49344;    // 200
    float* inp_s = sm + 49544;    // 32
    float* part  = sm + 49576;    // 8 x 32

    const int tid  = threadIdx.x;
    const int lane = tid & 31;
    const int w5   = (tid >> 5) * 5;
    const int row0 = blockIdx.x * MCTA;

    // ldmatrix per-lane base offset within an A buffer
    const int blk = lane >> 3, rr = lane & 7;
    const u32 aoff = (u32)(((blk & 1) * 8 + rr) * 432 + (blk >> 1) * 16);
    const u32 abase = smem_u32(ab) + aoff;

    // per-buffer handles: [p] selects double buffer 0/1
    u32 aH0[2], aL0[2], aH1[2], aL1[2];
    __nv_bfloat16 *H0h[2], *H0l[2], *H1h[2], *H1l[2];
#pragma unroll
    for (int p = 0; p < 2; p++) {
        aH0[p] = abase + (u32)(p * ABUF_B);
        aL0[p] = abase + (u32)((2 + p) * ABUF_B);
        aH1[p] = abase + (u32)((4 + p) * ABUF_B);
        aL1[p] = abase + (u32)((6 + p) * ABUF_B);
        H0h[p] = reinterpret_cast<__nv_bfloat16*>(ab + p * ABUF_B);
        H0l[p] = reinterpret_cast<__nv_bfloat16*>(ab + (2 + p) * ABUF_B);
        H1h[p] = reinterpret_cast<__nv_bfloat16*>(ab + (4 + p) * ABUF_B);
        H1l[p] = reinterpret_cast<__nv_bfloat16*>(ab + (6 + p) * ABUF_B);
    }

    // zero A buffers + c states; stage xs, vb, lin
    for (int i = tid; i < 40448; i += NTHR) sm[i] = 0.f;
    for (int i = tid; i < TLEN * MCTA; i += NTHR) {
        int t = i >> 5, r = i & 31;
        xs[i] = x[(row0 + r) * TLEN + t];
    }
    {
        const float* gv = &g_v[0][0];
        for (int i = tid; i < 6 * 800; i += NTHR) vb[i] = gv[i];
    }
    for (int i = tid; i < HID; i += NTHR) lin_s[i] = linW[i];
    __syncthreads();

    const float* wx0  = vb;
    const float* b0   = vb + 800;
    const float* b1   = vb + 1600;
    const float* dwx0 = vb + 2400;
    const float* db0  = vb + 3200;
    const float* db1  = vb + 4000;

    // ================= encoder: 1 barrier per step =================
    // State convention: h0(t) lives in buf[t&1]; h1(t) in buf[t&1].
    // h0(-1)=h1(-1)=0 live in buf1 (both buffers zeroed).

    {   // prologue: layer0 of t=0 (reads h0(-1) = buf1)
        float acc[2][5][4];
        acc_init(acc, b0, wx0, xs + 0, w5, lane);
        hgemm(g_Bf[0], aH0[1], aL0[1], w5, lane, acc);
        cell_epi(acc, c0s, H0h[0], H0l[0], w5, lane);
    }
    __syncthreads();

    for (int t = 1; t < TLEN; t++) {
        const int pr = (t - 1) & 1;     // h0(t-1), h1(t-1) target parity
        const int pw = t & 1;           // h0(t) parity; also h1(t-2) parity

        {   // layer1 of (t-1): b1 + Wih1*h0(t-1) + Whh1*h1(t-2)
            float acc[2][5][4];
            acc_init(acc, b1, (const float*)0, (const float*)0, w5, lane);
            hgemm(g_Bf[1], aH0[pr], aL0[pr], w5, lane, acc);
            hgemm(g_Bf[2], aH1[pw], aL1[pw], w5, lane, acc);
            cell_epi(acc, c1s, H1h[pr], H1l[pr], w5, lane);   // h1(t-1) -> buf[pr]
        }
        {   // layer0 of t: b0 + wx0*x[t] + Whh0*h0(t-1)   (independent of epi1 above)
            float acc[2][5][4];
            acc_init(acc, b0, wx0, xs + t * 32, w5, lane);
            hgemm(g_Bf[0], aH0[pr], aL0[pr], w5, lane, acc);
            cell_epi(acc, c0s, H0h[pw], H0l[pw], w5, lane);   // h0(t) -> buf[pw]
        }
        __syncthreads();
    }

    {   // tail: layer1 of t=127 (h0(127) in buf1, h1(126) in buf0)
        float acc[2][5][4];
        acc_init(acc, b1, (const float*)0, (const float*)0, w5, lane);
        hgemm(g_Bf[1], aH0[1], aL0[1], w5, lane, acc);
        hgemm(g_Bf[2], aH1[0], aL1[0], w5, lane, acc);
        cell_epi(acc, c1s, H1h[1], H1l[1], w5, lane);         // h1(127) -> buf1
    }
    // decoder initial input = x[:, T-1]
    if (tid < MCTA) inp_s[tid] = xs[(TLEN - 1) * 32 + tid];
    __syncthreads();

    const float lb = linb[0];

    // ================= decoder: 64 steps (R13 structure) =================
    // Continue parity: h0(d) -> buf[d&1], with h0(-1)=enc h0(127) in buf1. Same for h1.
    for (int d = 0; d < OUTLEN; d++) {
        const int pr = (d + 1) & 1;     // (d-1) parity
        const int pw = d & 1;

        {   // dec layer0
            float acc[2][5][4];
            acc_init(acc, db0, dwx0, inp_s, w5, lane);
            hgemm(g_Bf[3], aH0[pr], aL0[pr], w5, lane, acc);
            cell_epi(acc, c0s, H0h[pw], H0l[pw], w5, lane);
        }
        __syncthreads();

        {   // dec layer1
            float acc[2][5][4];
            acc_init(acc, db1, (const float*)0, (const float*)0, w5, lane);
            hgemm(g_Bf[4], aH0[pw], aL0[pw], w5, lane, acc);  // input = h0(d)
            hgemm(g_Bf[5], aH1[pr], aL1[pr], w5, lane, acc);  // recurrence h1(d-1)
            cell_epi(acc, c1s, H1h[pw], H1l[pw], w5, lane);
        }
        __syncthreads();

        // linear head on h1(d) (hi+lo), 8 groups x 25 units
        if (tid < 256) {
            int grp = tid >> 5, r = tid & 31;
            int ub = grp * 25;
            float s = 0.f;
#pragma unroll 5
            for (int u = 0; u < 25; u++) {
                int uu = ub + u;
                float hv = __bfloat162float(H1h[pw][r * ASTR + uu]) +
                           __bfloat162float(H1l[pw][r * ASTR + uu]);
                s += lin_s[uu] * hv;
            }
            part[grp * 32 + r] = s;
        }
        __syncthreads();
        if (tid < MCTA) {
            float s = lb;
#pragma unroll
            for (int g = 0; g < 8; g++) s += part[g * 32 + tid];
            out[(row0 + tid) * OUTLEN + d] = s;
            inp_s[tid] = s;
        }
        __syncthreads();
    }
}

extern "C" void kernel_launch(void* const* d_in, const int* in_sizes, int n_in,
                              void* d_out, int out_size)
{
    (void)in_sizes; (void)n_in; (void)out_size;
    const float* x     = (const float*)d_in[0];
    const float* eWih0 = (const float*)d_in[1];
    const float* eWhh0 = (const float*)d_in[2];
    const float* eb0   = (const float*)d_in[3];
    const float* eWih1 = (const float*)d_in[4];
    const float* eWhh1 = (const float*)d_in[5];
    const float* eb1   = (const float*)d_in[6];
    const float* dWih0 = (const float*)d_in[7];
    const float* dWhh0 = (const float*)d_in[8];
    const float* db0   = (const float*)d_in[9];
    const float* dWih1 = (const float*)d_in[10];
    const float* dWhh1 = (const float*)d_in[11];
    const float* db1   = (const float*)d_in[12];
    const float* linW  = (const float*)d_in[13];
    const float* linb  = (const float*)d_in[14];
    float* out = (float*)d_out;

    cudaFuncSetAttribute(lstm_kernel, cudaFuncAttributeMaxDynamicSharedMemorySize,
                         SMEM_FLOATS * (int)sizeof(float));

    prep_kernel<<<(FRAG_ELEMS + 255) / 256, 256>>>(eWhh0, eWih1, eWhh1, dWhh0, dWih1, dWhh1,
                                                   eWih0, eb0, eb1, dWih0, db0, db1);
    lstm_kernel<<<NBLK, NTHR, SMEM_FLOATS * (int)sizeof(float)>>>(x, linW, linb, out);
}

// round 16
// speedup vs baseline: 1.6670x; 1.3125x over previous
#include <cuda_runtime.h>
#include <cuda_fp16.h>

// LSTMForecastModel: B=4096, T=128, OUT=64, H=200.
// R15 = R14 skeleton, mma core switched bf16 3-term -> fp16 2-term:
//   W (static) split fp16 hi+lo (~22-bit effective), h single fp16.
//   20 mmas/kstep (was 30), 2 ldsm (was 4), 1 h-store in epilogue (was 2).
// h's fp16 rounding is fresh zero-mean noise per step (not systematic), W stays
// near-fp32 -> expected rel_err ~1e-4, tensor cycles cut by 1/3.

#define BATCH  4096
#define TLEN   128
#define OUTLEN 64
#define HID    200
#define MCTA   32
#define NTHR   640
#define NBLK   128
#define KSTEPS 13            // 13*16 = 208 >= 200 (zero padded)
#define NTILES 100           // 800 / 8
#define FRAG_ELEMS (KSTEPS * NTILES * 32)
#define ASTR   216           // A row stride in fp16 elems (432 B)
#define ABUF_B (32 * ASTR * 2)   // 13824 bytes per A buffer

typedef unsigned int u32;

// B fragments, per matrix: [s][jt][lane] -> uint4 {Bhi k01, Bhi k89, Blo k01, Blo k89}.
// 0=enc_Whh0 1=enc_Wih1 2=enc_Whh1 3=dec_Whh0 4=dec_Wih1 5=dec_Whh1
__device__ uint4 g_Bf[6][FRAG_ELEMS];
// vectors indexed by col n = u*4+g: 0=enc_Wih0 1=enc_b0 2=enc_b1 3=dec_Wih0 4=dec_b0 5=dec_b1
__device__ float g_v[6][800];

__device__ __forceinline__ void hsplit(float w, u32& hi, u32& lo) {
    __half h = __float2half_rn(w);
    __half l = __float2half_rn(w - __half2float(h));
    hi = (u32)__half_as_ushort(h);
    lo = (u32)__half_as_ushort(l);
}

__global__ void prep_kernel(const float* __restrict__ eWhh0, const float* __restrict__ eWih1,
                            const float* __restrict__ eWhh1, const float* __restrict__ dWhh0,
                            const float* __restrict__ dWih1, const float* __restrict__ dWhh1,
                            const float* __restrict__ eWih0, const float* __restrict__ eb0,
                            const float* __restrict__ eb1,  const float* __restrict__ dWih0,
                            const float* __restrict__ db0,  const float* __restrict__ db1)
{
    int idx = blockIdx.x * blockDim.x + threadIdx.x;
    if (idx < FRAG_ELEMS) {
        int lane = idx & 31;
        int sj   = idx >> 5;
        int jt   = sj % NTILES;
        int s    = sj / NTILES;
        int gid  = lane >> 2, tig = lane & 3;
        int n = jt * 8 + gid;
        int u = n >> 2, g = n & 3;
        int R = g * HID + u;
        int k0 = s * 16 + tig * 2;
        const float* srcs[6] = {eWhh0, eWih1, eWhh1, dWhh0, dWih1, dWhh1};
#pragma unroll
        for (int m = 0; m < 6; m++) {
            const float* src = srcs[m] + R * HID;
            float w00 = (k0     < HID) ? src[k0]     : 0.f;
            float w01 = (k0 + 1 < HID) ? src[k0 + 1] : 0.f;
            float w10 = (k0 + 8 < HID) ? src[k0 + 8] : 0.f;
            float w11 = (k0 + 9 < HID) ? src[k0 + 9] : 0.f;
            u32 h00, l00, h01, l01, h10, l10, h11, l11;
            hsplit(w00, h00, l00); hsplit(w01, h01, l01);
            hsplit(w10, h10, l10); hsplit(w11, h11, l11);
            uint4 v;
            v.x = h00 | (h01 << 16);
            v.y = h10 | (h11 << 16);
            v.z = l00 | (l01 << 16);
            v.w = l10 | (l11 << 16);
            g_Bf[m][idx] = v;
        }
    }
    if (idx < 800) {
        int u = idx >> 2, g = idx & 3;
        int sI = g * HID + u;
        g_v[0][idx] = eWih0[sI];
        g_v[1][idx] = eb0[sI];
        g_v[2][idx] = eb1[sI];
        g_v[3][idx] = dWih0[sI];
        g_v[4][idx] = db0[sI];
        g_v[5][idx] = db1[sI];
    }
}

// ---- device primitives ----
__device__ __forceinline__ u32 smem_u32(const void* p) {
    u32 a;
    asm("{ .reg .u64 t; cvta.to.shared.u64 t, %1; cvt.u32.u64 %0, t; }" : "=r"(a) : "l"(p));
    return a;
}
__device__ __forceinline__ void ldsm4(u32 (&d)[4], u32 addr) {
    asm volatile("ldmatrix.sync.aligned.m8n8.x4.shared.b16 {%0,%1,%2,%3}, [%4];"
                 : "=r"(d[0]), "=r"(d[1]), "=r"(d[2]), "=r"(d[3]) : "r"(addr));
}
__device__ __forceinline__ void mma16816(float (&c)[4], const u32 (&a)[4], u32 b0, u32 b1) {
    asm volatile("mma.sync.aligned.m16n8k16.row.col.f32.f16.f16.f32 "
                 "{%0,%1,%2,%3},{%4,%5,%6,%7},{%8,%9},{%0,%1,%2,%3};"
                 : "+f"(c[0]), "+f"(c[1]), "+f"(c[2]), "+f"(c[3])
                 : "r"(a[0]), "r"(a[1]), "r"(a[2]), "r"(a[3]), "r"(b0), "r"(b1));
}
__device__ __forceinline__ float sigf(float x)   { return __fdividef(1.f, 1.f + __expf(-x)); }
__device__ __forceinline__ float tanh_f(float x) { return 1.f - __fdividef(2.f, 1.f + __expf(2.f * x)); }

// gates += A @ (Bhi+Blo)^T, A single fp16.
// Per kstep: 5 B LDG.128 up front (MLP=5), 2 ldsm, 20 mmas.
__device__ __forceinline__ void hgemm(const uint4* __restrict__ Bf, u32 aA,
                                      int w5, int lane, float (&acc)[2][5][4])
{
    const uint4* __restrict__ bp = Bf + w5 * 32 + lane;
#pragma unroll 1
    for (int s = 0; s < KSTEPS; s++) {
        uint4 b0 = bp[0];
        uint4 b1 = bp[32];
        uint4 b2 = bp[64];
        uint4 b3 = bp[96];
        uint4 b4 = bp[128];
        u32 ah[2][4];
        ldsm4(ah[0], aA);
        ldsm4(ah[1], aA + 16 * 432);
        aA += 32;

        mma16816(acc[0][0], ah[0], b0.x, b0.y);
        mma16816(acc[1][0], ah[1], b0.x, b0.y);
        mma16816(acc[0][0], ah[0], b0.z, b0.w);
        mma16816(acc[1][0], ah[1], b0.z, b0.w);

        mma16816(acc[0][1], ah[0], b1.x, b1.y);
        mma16816(acc[1][1], ah[1], b1.x, b1.y);
        mma16816(acc[0][1], ah[0], b1.z, b1.w);
        mma16816(acc[1][1], ah[1], b1.z, b1.w);

        mma16816(acc[0][2], ah[0], b2.x, b2.y);
        mma16816(acc[1][2], ah[1], b2.x, b2.y);
        mma16816(acc[0][2], ah[0], b2.z, b2.w);
        mma16816(acc[1][2], ah[1], b2.z, b2.w);

        mma16816(acc[0][3], ah[0], b3.x, b3.y);
        mma16816(acc[1][3], ah[1], b3.x, b3.y);
        mma16816(acc[0][3], ah[0], b3.z, b3.w);
        mma16816(acc[1][3], ah[1], b3.z, b3.w);

        mma16816(acc[0][4], ah[0], b4.x, b4.y);
        mma16816(acc[1][4], ah[1], b4.x, b4.y);
        mma16816(acc[0][4], ah[0], b4.z, b4.w);
        mma16816(acc[1][4], ah[1], b4.z, b4.w);

        bp += NTILES * 32;
    }
}

// acc init: bias + (optional) rank-1 wx * x[row].
__device__ __forceinline__ void acc_init(float (&acc)[2][5][4], const float* __restrict__ bias,
                                         const float* __restrict__ wx, const float* __restrict__ xrow,
                                         int w5, int lane)
{
    int gid = lane >> 2, tig = lane & 3;
#pragma unroll
    for (int mt = 0; mt < 2; mt++) {
        float xa = 0.f, xb = 0.f;
        if (xrow) { xa = xrow[mt * 16 + gid]; xb = xrow[mt * 16 + gid + 8]; }
#pragma unroll
        for (int j = 0; j < 5; j++) {
            int col0 = (w5 + j) * 8 + tig * 2;
            float b0v = bias[col0], b1v = bias[col0 + 1];
            if (xrow) {
                float w0 = wx[col0], w1 = wx[col0 + 1];
                acc[mt][j][0] = b0v + w0 * xa;
                acc[mt][j][1] = b1v + w1 * xa;
                acc[mt][j][2] = b0v + w0 * xb;
                acc[mt][j][3] = b1v + w1 * xb;
            } else {
                acc[mt][j][0] = b0v; acc[mt][j][1] = b1v;
                acc[mt][j][2] = b0v; acc[mt][j][3] = b1v;
            }
        }
    }
}

// Cell epilogue: even tig holds (i,f), odd (g,o) of the same unit; shfl_xor(1).
// Writes c (fp32, owner-only) and h as SINGLE fp16 into the given A buffer.
__device__ __forceinline__ void cell_epi(float (&acc)[2][5][4], float* __restrict__ cs,
                                         __half* __restrict__ Ah, int w5, int lane)
{
    int gid = lane >> 2, tig = lane & 3;
    bool ev = !(tig & 1);
#pragma unroll
    for (int mt = 0; mt < 2; mt++) {
#pragma unroll
        for (int j = 0; j < 5; j++) {
            int u = 2 * (w5 + j) + (tig >> 1);
            float o0 = __shfl_xor_sync(0xffffffffu, acc[mt][j][0], 1);
            float o1 = __shfl_xor_sync(0xffffffffu, acc[mt][j][1], 1);
            float o2 = __shfl_xor_sync(0xffffffffu, acc[mt][j][2], 1);
            float o3 = __shfl_xor_sync(0xffffffffu, acc[mt][j][3], 1);
            float gi, gf, gg, go;
            int row;
            if (ev) { gi = acc[mt][j][0]; gf = acc[mt][j][1]; gg = o0; go = o1; row = mt * 16 + gid; }
            else    { gi = o2; gf = o3; gg = acc[mt][j][2]; go = acc[mt][j][3]; row = mt * 16 + gid + 8; }
            float cv = cs[u * 32 + row];
            float cn = sigf(gf) * cv + sigf(gi) * tanh_f(gg);
            cs[u * 32 + row] = cn;
            float h = sigf(go) * tanh_f(cn);
            Ah[row * ASTR + u] = __float2half_rn(h);
        }
    }
}

// smem floats: Abufs 4*13824B = 13824 | c0 6400 | c1 6400 | xs 4096 | vb 4800 |
//              lin 200 | inp 32 | part 256  = 36008 floats (144,032 B)
#define SMEM_FLOATS 36008

__global__ void __launch_bounds__(NTHR, 1)
lstm_kernel(const float* __restrict__ x, const float* __restrict__ linW,
            const float* __restrict__ linb, float* __restrict__ out)
{
    extern __shared__ float sm[];
    char* ab = reinterpret_cast<char*>(sm);
    // A buffers (fp16, ABUF_B each): [0,1]=h0 buf0/1, [2,3]=h1 buf0/1
    float* c0s   = sm + 13824;
    float* c1s   = sm + 20224;
    float* xs    = sm + 26624;    // [t=128][row=32]
    float* vb    = sm + 30720;    // 6 x 800
    float* lin_s = sm + 35520;    // 200
    float* inp_s = sm + 35720;    // 32
    float* part  = sm + 35752;    // 8 x 32

    const int tid  = threadIdx.x;
    const int lane = tid & 31;
    const int w5   = (tid >> 5) * 5;
    const int row0 = blockIdx.x * MCTA;

    // ldmatrix per-lane base offset within an A buffer
    const int blk = lane >> 3, rr = lane & 7;
    const u32 aoff = (u32)(((blk & 1) * 8 + rr) * 432 + (blk >> 1) * 16);
    const u32 abase = smem_u32(ab) + aoff;

    // per-buffer handles: [p] = double buffer 0/1
    u32 aH0[2], aH1[2];
    __half *H0[2], *H1[2];
#pragma unroll
    for (int p = 0; p < 2; p++) {
        aH0[p] = abase + (u32)(p * ABUF_B);
        aH1[p] = abase + (u32)((2 + p) * ABUF_B);
        H0[p] = reinterpret_cast<__half*>(ab + p * ABUF_B);
        H1[p] = reinterpret_cast<__half*>(ab + (2 + p) * ABUF_B);
    }

    // zero A buffers + c states; stage xs, vb, lin
    for (int i = tid; i < 26624; i += NTHR) sm[i] = 0.f;
    for (int i = tid; i < TLEN * MCTA; i += NTHR) {
        int t = i >> 5, r = i & 31;
        xs[i] = x[(row0 + r) * TLEN + t];
    }
    {
        const float* gv = &g_v[0][0];
        for (int i = tid; i < 6 * 800; i += NTHR) vb[i] = gv[i];
    }
    for (int i = tid; i < HID; i += NTHR) lin_s[i] = linW[i];
    __syncthreads();

    const float* wx0  = vb;
    const float* b0   = vb + 800;
    const float* b1   = vb + 1600;
    const float* dwx0 = vb + 2400;
    const float* db0  = vb + 3200;
    const float* db1  = vb + 4000;

    // ================= encoder: 1 barrier per step =================
    // h0(t) lives in buf[t&1]; h1(t) in buf[t&1]. h0(-1)=h1(-1)=0 in buf1.

    {   // prologue: layer0 of t=0
        float acc[2][5][4];
        acc_init(acc, b0, wx0, xs + 0, w5, lane);
        hgemm(g_Bf[0], aH0[1], w5, lane, acc);
        cell_epi(acc, c0s, H0[0], w5, lane);
    }
    __syncthreads();

    for (int t = 1; t < TLEN; t++) {
        const int pr = (t - 1) & 1;
        const int pw = t & 1;

        {   // layer1 of (t-1): b1 + Wih1*h0(t-1) + Whh1*h1(t-2)
            float acc[2][5][4];
            acc_init(acc, b1, (const float*)0, (const float*)0, w5, lane);
            hgemm(g_Bf[1], aH0[pr], w5, lane, acc);
            hgemm(g_Bf[2], aH1[pw], w5, lane, acc);
            cell_epi(acc, c1s, H1[pr], w5, lane);             // h1(t-1) -> buf[pr]
        }
        {   // layer0 of t: b0 + wx0*x[t] + Whh0*h0(t-1)
            float acc[2][5][4];
            acc_init(acc, b0, wx0, xs + t * 32, w5, lane);
            hgemm(g_Bf[0], aH0[pr], w5, lane, acc);
            cell_epi(acc, c0s, H0[pw], w5, lane);             // h0(t) -> buf[pw]
        }
        __syncthreads();
    }

    {   // tail: layer1 of t=127 (h0(127) buf1, h1(126) buf0)
        float acc[2][5][4];
        acc_init(acc, b1, (const float*)0, (const float*)0, w5, lane);
        hgemm(g_Bf[1], aH0[1], w5, lane, acc);
        hgemm(g_Bf[2], aH1[0], w5, lane, acc);
        cell_epi(acc, c1s, H1[1], w5, lane);                  // h1(127) -> buf1
    }
    if (tid < MCTA) inp_s[tid] = xs[(TLEN - 1) * 32 + tid];
    __syncthreads();

    const float lb = linb[0];

    // ================= decoder: 64 steps =================
    for (int d = 0; d < OUTLEN; d++) {
        const int pr = (d + 1) & 1;
        const int pw = d & 1;

        {   // dec layer0
            float acc[2][5][4];
            acc_init(acc, db0, dwx0, inp_s, w5, lane);
            hgemm(g_Bf[3], aH0[pr], w5, lane, acc);
            cell_epi(acc, c0s, H0[pw], w5, lane);
        }
        __syncthreads();

        {   // dec layer1
            float acc[2][5][4];
            acc_init(acc, db1, (const float*)0, (const float*)0, w5, lane);
            hgemm(g_Bf[4], aH0[pw], w5, lane, acc);           // input = h0(d)
            hgemm(g_Bf[5], aH1[pr], w5, lane, acc);           // recurrence h1(d-1)
            cell_epi(acc, c1s, H1[pw], w5, lane);
        }
        __syncthreads();

        // linear head on h1(d), 8 groups x 25 units
        if (tid < 256) {
            int grp = tid >> 5, r = tid & 31;
            int ub = grp * 25;
            float s = 0.f;
#pragma unroll 5
            for (int u = 0; u < 25; u++) {
                int uu = ub + u;
                s += lin_s[uu] * __half2float(H1[pw][r * ASTR + uu]);
            }
            part[grp * 32 + r] = s;
        }
        __syncthreads();
        if (tid < MCTA) {
            float s = lb;
#pragma unroll
            for (int g = 0; g < 8; g++) s += part[g * 32 + tid];
            out[(row0 + tid) * OUTLEN + d] = s;
            inp_s[tid] = s;
        }
        __syncthreads();
    }
}

extern "C" void kernel_launch(void* const* d_in, const int* in_sizes, int n_in,
                              void* d_out, int out_size)
{
    (void)in_sizes; (void)n_in; (void)out_size;
    const float* x     = (const float*)d_in[0];
    const float* eWih0 = (const float*)d_in[1];
    const float* eWhh0 = (const float*)d_in[2];
    const float* eb0   = (const float*)d_in[3];
    const float* eWih1 = (const float*)d_in[4];
    const float* eWhh1 = (const float*)d_in[5];
    const float* eb1   = (const float*)d_in[6];
    const float* dWih0 = (const float*)d_in[7];
    const float* dWhh0 = (const float*)d_in[8];
    const float* db0   = (const float*)d_in[9];
    const float* dWih1 = (const float*)d_in[10];
    const float* dWhh1 = (const float*)d_in[11];
    const float* db1   = (const float*)d_in[12];
    const float* linW  = (const float*)d_in[13];
    const float* linb  = (const float*)d_in[14];
    float* out = (float*)d_out;

    cudaFuncSetAttribute(lstm_kernel, cudaFuncAttributeMaxDynamicSharedMemorySize,
                         SMEM_FLOATS * (int)sizeof(float));

    prep_kernel<<<(FRAG_ELEMS + 255) / 256, 256>>>(eWhh0, eWih1, eWhh1, dWhh0, dWih1, dWhh1,
                                                   eWih0, eb0, eb1, dWih0, db0, db1);
    lstm_kernel<<<NBLK, NTHR, SMEM_FLOATS * (int)sizeof(float)>>>(x, linW, linb, out);
}

// round 17
// speedup vs baseline: 1.6958x; 1.0173x over previous
#include <cuda_runtime.h>
#include <cuda_fp16.h>

// LSTMForecastModel: B=4096, T=128, OUT=64, H=200.
// R16 = R15 (fp16 2-term: W split hi+lo, h single fp16, 20 mma/kstep)
//  + WARP-PARITY STAGGERED encoder body: even warps run [layer1; layer0],
//    odd warps run [layer0; layer1]. The two halves are independent given
//    body-entry state, so at any instant ~half the warps do MUFU epilogue
//    while half issue tensor mmas -> epilogue and post-barrier load bursts
//    no longer drain the tensor pipe chip-wide.

#define BATCH  4096
#define TLEN   128
#define OUTLEN 64
#define HID    200
#define MCTA   32
#define NTHR   640
#define NBLK   128
#define KSTEPS 13            // 13*16 = 208 >= 200 (zero padded)
#define NTILES 100           // 800 / 8
#define FRAG_ELEMS (KSTEPS * NTILES * 32)
#define ASTR   216           // A row stride in fp16 elems (432 B)
#define ABUF_B (32 * ASTR * 2)   // 13824 bytes per A buffer

typedef unsigned int u32;

// B fragments, per matrix: [s][jt][lane] -> uint4 {Bhi k01, Bhi k89, Blo k01, Blo k89}.
// 0=enc_Whh0 1=enc_Wih1 2=enc_Whh1 3=dec_Whh0 4=dec_Wih1 5=dec_Whh1
__device__ uint4 g_Bf[6][FRAG_ELEMS];
// vectors indexed by col n = u*4+g: 0=enc_Wih0 1=enc_b0 2=enc_b1 3=dec_Wih0 4=dec_b0 5=dec_b1
__device__ float g_v[6][800];

__device__ __forceinline__ void hsplit(float w, u32& hi, u32& lo) {
    __half h = __float2half_rn(w);
    __half l = __float2half_rn(w - __half2float(h));
    hi = (u32)__half_as_ushort(h);
    lo = (u32)__half_as_ushort(l);
}

__global__ void prep_kernel(const float* __restrict__ eWhh0, const float* __restrict__ eWih1,
                            const float* __restrict__ eWhh1, const float* __restrict__ dWhh0,
                            const float* __restrict__ dWih1, const float* __restrict__ dWhh1,
                            const float* __restrict__ eWih0, const float* __restrict__ eb0,
                            const float* __restrict__ eb1,  const float* __restrict__ dWih0,
                            const float* __restrict__ db0,  const float* __restrict__ db1)
{
    int idx = blockIdx.x * blockDim.x + threadIdx.x;
    if (idx < FRAG_ELEMS) {
        int lane = idx & 31;
        int sj   = idx >> 5;
        int jt   = sj % NTILES;
        int s    = sj / NTILES;
        int gid  = lane >> 2, tig = lane & 3;
        int n = jt * 8 + gid;
        int u = n >> 2, g = n & 3;
        int R = g * HID + u;
        int k0 = s * 16 + tig * 2;
        const float* srcs[6] = {eWhh0, eWih1, eWhh1, dWhh0, dWih1, dWhh1};
#pragma unroll
        for (int m = 0; m < 6; m++) {
            const float* src = srcs[m] + R * HID;
            float w00 = (k0     < HID) ? src[k0]     : 0.f;
            float w01 = (k0 + 1 < HID) ? src[k0 + 1] : 0.f;
            float w10 = (k0 + 8 < HID) ? src[k0 + 8] : 0.f;
            float w11 = (k0 + 9 < HID) ? src[k0 + 9] : 0.f;
            u32 h00, l00, h01, l01, h10, l10, h11, l11;
            hsplit(w00, h00, l00); hsplit(w01, h01, l01);
            hsplit(w10, h10, l10); hsplit(w11, h11, l11);
            uint4 v;
            v.x = h00 | (h01 << 16);
            v.y = h10 | (h11 << 16);
            v.z = l00 | (l01 << 16);
            v.w = l10 | (l11 << 16);
            g_Bf[m][idx] = v;
        }
    }
    if (idx < 800) {
        int u = idx >> 2, g = idx & 3;
        int sI = g * HID + u;
        g_v[0][idx] = eWih0[sI];
        g_v[1][idx] = eb0[sI];
        g_v[2][idx] = eb1[sI];
        g_v[3][idx] = dWih0[sI];
        g_v[4][idx] = db0[sI];
        g_v[5][idx] = db1[sI];
    }
}

// ---- device primitives ----
__device__ __forceinline__ u32 smem_u32(const void* p) {
    u32 a;
    asm("{ .reg .u64 t; cvta.to.shared.u64 t, %1; cvt.u32.u64 %0, t; }" : "=r"(a) : "l"(p));
    return a;
}
__device__ __forceinline__ void ldsm4(u32 (&d)[4], u32 addr) {
    asm volatile("ldmatrix.sync.aligned.m8n8.x4.shared.b16 {%0,%1,%2,%3}, [%4];"
                 : "=r"(d[0]), "=r"(d[1]), "=r"(d[2]), "=r"(d[3]) : "r"(addr));
}
__device__ __forceinline__ void mma16816(float (&c)[4], const u32 (&a)[4], u32 b0, u32 b1) {
    asm volatile("mma.sync.aligned.m16n8k16.row.col.f32.f16.f16.f32 "
                 "{%0,%1,%2,%3},{%4,%5,%6,%7},{%8,%9},{%0,%1,%2,%3};"
                 : "+f"(c[0]), "+f"(c[1]), "+f"(c[2]), "+f"(c[3])
                 : "r"(a[0]), "r"(a[1]), "r"(a[2]), "r"(a[3]), "r"(b0), "r"(b1));
}
__device__ __forceinline__ float sigf(float x)   { return __fdividef(1.f, 1.f + __expf(-x)); }
__device__ __forceinline__ float tanh_f(float x) { return 1.f - __fdividef(2.f, 1.f + __expf(2.f * x)); }

// gates += A @ (Bhi+Blo)^T, A single fp16.
// Per kstep: 5 B LDG.128 up front (MLP=5), 2 ldsm, 20 mmas.
__device__ __forceinline__ void hgemm(const uint4* __restrict__ Bf, u32 aA,
                                      int w5, int lane, float (&acc)[2][5][4])
{
    const uint4* __restrict__ bp = Bf + w5 * 32 + lane;
#pragma unroll 1
    for (int s = 0; s < KSTEPS; s++) {
        uint4 b0 = bp[0];
        uint4 b1 = bp[32];
        uint4 b2 = bp[64];
        uint4 b3 = bp[96];
        uint4 b4 = bp[128];
        u32 ah[2][4];
        ldsm4(ah[0], aA);
        ldsm4(ah[1], aA + 16 * 432);
        aA += 32;

        mma16816(acc[0][0], ah[0], b0.x, b0.y);
        mma16816(acc[1][0], ah[1], b0.x, b0.y);
        mma16816(acc[0][0], ah[0], b0.z, b0.w);
        mma16816(acc[1][0], ah[1], b0.z, b0.w);

        mma16816(acc[0][1], ah[0], b1.x, b1.y);
        mma16816(acc[1][1], ah[1], b1.x, b1.y);
        mma16816(acc[0][1], ah[0], b1.z, b1.w);
        mma16816(acc[1][1], ah[1], b1.z, b1.w);

        mma16816(acc[0][2], ah[0], b2.x, b2.y);
        mma16816(acc[1][2], ah[1], b2.x, b2.y);
        mma16816(acc[0][2], ah[0], b2.z, b2.w);
        mma16816(acc[1][2], ah[1], b2.z, b2.w);

        mma16816(acc[0][3], ah[0], b3.x, b3.y);
        mma16816(acc[1][3], ah[1], b3.x, b3.y);
        mma16816(acc[0][3], ah[0], b3.z, b3.w);
        mma16816(acc[1][3], ah[1], b3.z, b3.w);

        mma16816(acc[0][4], ah[0], b4.x, b4.y);
        mma16816(acc[1][4], ah[1], b4.x, b4.y);
        mma16816(acc[0][4], ah[0], b4.z, b4.w);
        mma16816(acc[1][4], ah[1], b4.z, b4.w);

        bp += NTILES * 32;
    }
}

// acc init: bias + (optional) rank-1 wx * x[row].
__device__ __forceinline__ void acc_init(float (&acc)[2][5][4], const float* __restrict__ bias,
                                         const float* __restrict__ wx, const float* __restrict__ xrow,
                                         int w5, int lane)
{
    int gid = lane >> 2, tig = lane & 3;
#pragma unroll
    for (int mt = 0; mt < 2; mt++) {
        float xa = 0.f, xb = 0.f;
        if (xrow) { xa = xrow[mt * 16 + gid]; xb = xrow[mt * 16 + gid + 8]; }
#pragma unroll
        for (int j = 0; j < 5; j++) {
            int col0 = (w5 + j) * 8 + tig * 2;
            float b0v = bias[col0], b1v = bias[col0 + 1];
            if (xrow) {
                float w0 = wx[col0], w1 = wx[col0 + 1];
                acc[mt][j][0] = b0v + w0 * xa;
                acc[mt][j][1] = b1v + w1 * xa;
                acc[mt][j][2] = b0v + w0 * xb;
                acc[mt][j][3] = b1v + w1 * xb;
            } else {
                acc[mt][j][0] = b0v; acc[mt][j][1] = b1v;
                acc[mt][j][2] = b0v; acc[mt][j][3] = b1v;
            }
        }
    }
}

// Cell epilogue: even tig holds (i,f), odd (g,o) of the same unit; shfl_xor(1).
// Writes c (fp32, owner-only) and h as SINGLE fp16 into the given A buffer.
__device__ __forceinline__ void cell_epi(float (&acc)[2][5][4], float* __restrict__ cs,
                                         __half* __restrict__ Ah, int w5, int lane)
{
    int gid = lane >> 2, tig = lane & 3;
    bool ev = !(tig & 1);
#pragma unroll
    for (int mt = 0; mt < 2; mt++) {
#pragma unroll
        for (int j = 0; j < 5; j++) {
            int u = 2 * (w5 + j) + (tig >> 1);
            float o0 = __shfl_xor_sync(0xffffffffu, acc[mt][j][0], 1);
            float o1 = __shfl_xor_sync(0xffffffffu, acc[mt][j][1], 1);
            float o2 = __shfl_xor_sync(0xffffffffu, acc[mt][j][2], 1);
            float o3 = __shfl_xor_sync(0xffffffffu, acc[mt][j][3], 1);
            float gi, gf, gg, go;
            int row;
            if (ev) { gi = acc[mt][j][0]; gf = acc[mt][j][1]; gg = o0; go = o1; row = mt * 16 + gid; }
            else    { gi = o2; gf = o3; gg = acc[mt][j][2]; go = acc[mt][j][3]; row = mt * 16 + gid + 8; }
            float cv = cs[u * 32 + row];
            float cn = sigf(gf) * cv + sigf(gi) * tanh_f(gg);
            cs[u * 32 + row] = cn;
            float h = sigf(go) * tanh_f(cn);
            Ah[row * ASTR + u] = __float2half_rn(h);
        }
    }
}

// smem floats: Abufs 4*13824B = 13824 | c0 6400 | c1 6400 | xs 4096 | vb 4800 |
//              lin 200 | inp 32 | part 256  = 36008 floats (144,032 B)
#define SMEM_FLOATS 36008

__global__ void __launch_bounds__(NTHR, 1)
lstm_kernel(const float* __restrict__ x, const float* __restrict__ linW,
            const float* __restrict__ linb, float* __restrict__ out)
{
    extern __shared__ float sm[];
    char* ab = reinterpret_cast<char*>(sm);
    // A buffers (fp16, ABUF_B each): [0,1]=h0 buf0/1, [2,3]=h1 buf0/1
    float* c0s   = sm + 13824;
    float* c1s   = sm + 20224;
    float* xs    = sm + 26624;    // [t=128][row=32]
    float* vb    = sm + 30720;    // 6 x 800
    float* lin_s = sm + 35520;    // 200
    float* inp_s = sm + 35720;    // 32
    float* part  = sm + 35752;    // 8 x 32

    const int tid  = threadIdx.x;
    const int lane = tid & 31;
    const int wid  = tid >> 5;
    const int w5   = wid * 5;
    const bool wEven = (wid & 1) == 0;
    const int row0 = blockIdx.x * MCTA;

    // ldmatrix per-lane base offset within an A buffer
    const int blk = lane >> 3, rr = lane & 7;
    const u32 aoff = (u32)(((blk & 1) * 8 + rr) * 432 + (blk >> 1) * 16);
    const u32 abase = smem_u32(ab) + aoff;

    // per-buffer handles: [p] = double buffer 0/1
    u32 aH0[2], aH1[2];
    __half *H0[2], *H1[2];
#pragma unroll
    for (int p = 0; p < 2; p++) {
        aH0[p] = abase + (u32)(p * ABUF_B);
        aH1[p] = abase + (u32)((2 + p) * ABUF_B);
        H0[p] = reinterpret_cast<__half*>(ab + p * ABUF_B);
        H1[p] = reinterpret_cast<__half*>(ab + (2 + p) * ABUF_B);
    }

    // zero A buffers + c states; stage xs, vb, lin
    for (int i = tid; i < 26624; i += NTHR) sm[i] = 0.f;
    for (int i = tid; i < TLEN * MCTA; i += NTHR) {
        int t = i >> 5, r = i & 31;
        xs[i] = x[(row0 + r) * TLEN + t];
    }
    {
        const float* gv = &g_v[0][0];
        for (int i = tid; i < 6 * 800; i += NTHR) vb[i] = gv[i];
    }
    for (int i = tid; i < HID; i += NTHR) lin_s[i] = linW[i];
    __syncthreads();

    const float* wx0  = vb;
    const float* b0   = vb + 800;
    const float* b1   = vb + 1600;
    const float* dwx0 = vb + 2400;
    const float* db0  = vb + 3200;
    const float* db1  = vb + 4000;

    // ================= encoder: 1 barrier per step, staggered warps =================
    // h0(t) lives in buf[t&1]; h1(t) in buf[t&1]. h0(-1)=h1(-1)=0 in buf1.

    {   // prologue: layer0 of t=0
        float acc[2][5][4];
        acc_init(acc, b0, wx0, xs + 0, w5, lane);
        hgemm(g_Bf[0], aH0[1], w5, lane, acc);
        cell_epi(acc, c0s, H0[0], w5, lane);
    }
    __syncthreads();

    for (int t = 1; t < TLEN; t++) {
        const int pr = (t - 1) & 1;
        const int pw = t & 1;

        if (wEven) {
            {   // layer1 of (t-1)
                float acc[2][5][4];
                acc_init(acc, b1, (const float*)0, (const float*)0, w5, lane);
                hgemm(g_Bf[1], aH0[pr], w5, lane, acc);
                hgemm(g_Bf[2], aH1[pw], w5, lane, acc);
                cell_epi(acc, c1s, H1[pr], w5, lane);          // h1(t-1) -> buf[pr]
            }
            {   // layer0 of t
                float acc[2][5][4];
                acc_init(acc, b0, wx0, xs + t * 32, w5, lane);
                hgemm(g_Bf[0], aH0[pr], w5, lane, acc);
                cell_epi(acc, c0s, H0[pw], w5, lane);          // h0(t) -> buf[pw]
            }
        } else {
            {   // layer0 of t FIRST (independent of layer1 outputs this body)
                float acc[2][5][4];
                acc_init(acc, b0, wx0, xs + t * 32, w5, lane);
                hgemm(g_Bf[0], aH0[pr], w5, lane, acc);
                cell_epi(acc, c0s, H0[pw], w5, lane);
            }
            {   // layer1 of (t-1)
                float acc[2][5][4];
                acc_init(acc, b1, (const float*)0, (const float*)0, w5, lane);
                hgemm(g_Bf[1], aH0[pr], w5, lane, acc);
                hgemm(g_Bf[2], aH1[pw], w5, lane, acc);
                cell_epi(acc, c1s, H1[pr], w5, lane);
            }
        }
        __syncthreads();
    }

    {   // tail: layer1 of t=127 (h0(127) buf1, h1(126) buf0)
        float acc[2][5][4];
        acc_init(acc, b1, (const float*)0, (const float*)0, w5, lane);
        hgemm(g_Bf[1], aH0[1], w5, lane, acc);
        hgemm(g_Bf[2], aH1[0], w5, lane, acc);
        cell_epi(acc, c1s, H1[1], w5, lane);                  // h1(127) -> buf1
    }
    if (tid < MCTA) inp_s[tid] = xs[(TLEN - 1) * 32 + tid];
    __syncthreads();

    const float lb = linb[0];

    // ================= decoder: 64 steps =================
    for (int d = 0; d < OUTLEN; d++) {
        const int pr = (d + 1) & 1;
        const int pw = d & 1;

        {   // dec layer0
            float acc[2][5][4];
            acc_init(acc, db0, dwx0, inp_s, w5, lane);
            hgemm(g_Bf[3], aH0[pr], w5, lane, acc);
            cell_epi(acc, c0s, H0[pw], w5, lane);
        }
        __syncthreads();

        {   // dec layer1
            float acc[2][5][4];
            acc_init(acc, db1, (const float*)0, (const float*)0, w5, lane);
            hgemm(g_Bf[4], aH0[pw], w5, lane, acc);           // input = h0(d)
            hgemm(g_Bf[5], aH1[pr], w5, lane, acc);           // recurrence h1(d-1)
            cell_epi(acc, c1s, H1[pw], w5, lane);
        }
        __syncthreads();

        // linear head on h1(d), 8 groups x 25 units
        if (tid < 256) {
            int grp = tid >> 5, r = tid & 31;
            int ub = grp * 25;
            float s = 0.f;
#pragma unroll 5
            for (int u = 0; u < 25; u++) {
                int uu = ub + u;
                s += lin_s[uu] * __half2float(H1[pw][r * ASTR + uu]);
            }
            part[grp * 32 + r] = s;
        }
        __syncthreads();
        if (tid < MCTA) {
            float s = lb;
#pragma unroll
            for (int g = 0; g < 8; g++) s += part[g * 32 + tid];
            out[(row0 + tid) * OUTLEN + d] = s;
            inp_s[tid] = s;
        }
        __syncthreads();
    }
}

extern "C" void kernel_launch(void* const* d_in, const int* in_sizes, int n_in,
                              void* d_out, int out_size)
{
    (void)in_sizes; (void)n_in; (void)out_size;
    const float* x     = (const float*)d_in[0];
    const float* eWih0 = (const float*)d_in[1];
    const float* eWhh0 = (const float*)d_in[2];
    const float* eb0   = (const float*)d_in[3];
    const float* eWih1 = (const float*)d_in[4];
    const float* eWhh1 = (const float*)d_in[5];
    const float* eb1   = (const float*)d_in[6];
    const float* dWih0 = (const float*)d_in[7];
    const float* dWhh0 = (const float*)d_in[8];
    const float* db0   = (const float*)d_in[9];
    const float* dWih1 = (const float*)d_in[10];
    const float* dWhh1 = (const float*)d_in[11];
    const float* db1   = (const float*)d_in[12];
    const float* linW  = (const float*)d_in[13];
    const float* linb  = (const float*)d_in[14];
    float* out = (float*)d_out;

    cudaFuncSetAttribute(lstm_kernel, cudaFuncAttributeMaxDynamicSharedMemorySize,
                         SMEM_FLOATS * (int)sizeof(float));

    prep_kernel<<<(FRAG_ELEMS + 255) / 256, 256>>>(eWhh0, eWih1, eWhh1, dWhh0, dWih1, dWhh1,
                                                   eWih0, eb0, eb1, dWih0, db0, db1);
    lstm_kernel<<<NBLK, NTHR, SMEM_FLOATS * (int)sizeof(float)>>>(x, linW, linb, out);
}